// round 15
// baseline (speedup 1.0000x reference)
#include <cuda_runtime.h>
#include <cuda_fp16.h>
#include <cstdint>

#define T_STEPS 50
#define FEAT    14
#define MDIM    3
#define DT_     0.1f
#define ALPHA_  0.3f
#define DUMMY_DX_ 50.0f
#define ROWS    256
#define THREADS 512
#define NWARP   16

// ---------------- helpers ----------------
__device__ __forceinline__ void ffma2(unsigned long long &acc,
                                      unsigned long long a, unsigned long long b) {
    asm("fma.rn.f32x2 %0, %1, %2, %0;" : "+l"(acc) : "l"(a), "l"(b));
}
__device__ __forceinline__ unsigned long long pk(float lo, float hi) {
    unsigned long long r;
    asm("mov.b64 %0, {%1, %2};" : "=l"(r) : "f"(lo), "f"(hi));
    return r;
}
__device__ __forceinline__ float2 upk(unsigned long long v) {
    float2 f;
    asm("mov.b64 {%0, %1}, %2;" : "=f"(f.x), "=f"(f.y) : "l"(v));
    return f;
}
// packed f16x2: high half = cvt(a), low half = cvt(b)
__device__ __forceinline__ unsigned cvt2h(float hi, float lo) {
    unsigned r;
    asm("cvt.rn.f16x2.f32 %0, %1, %2;" : "=r"(r) : "f"(hi), "f"(lo));
    return r;
}
__device__ __forceinline__ float2 unpk2h(unsigned u) {
    __half2 h = *reinterpret_cast<__half2*>(&u);
    return __half22float2(h);          // .x = lo, .y = hi
}

__device__ __forceinline__ void mma16816(float &d0, float &d1, float &d2, float &d3,
                                         unsigned a0, unsigned a1, unsigned a2, unsigned a3,
                                         unsigned b0, unsigned b1) {
    asm("mma.sync.aligned.m16n8k16.row.col.f32.f16.f16.f32 "
        "{%0,%1,%2,%3}, {%4,%5,%6,%7}, {%8,%9}, {%0,%1,%2,%3};"
        : "+f"(d0), "+f"(d1), "+f"(d2), "+f"(d3)
        : "r"(a0), "r"(a1), "r"(a2), "r"(a3), "r"(b0), "r"(b1));
}

// ---------------- smem (~103KB) ----------------
struct __align__(16) Smem {
    unsigned bfragH[8 * 8 * 32 * 4];          // 32KB  W2 fp16 frags [((kt*8+q)*32+lam)*4+u]
    unsigned scratch32[8 * 8 * 32 * 4];       // 32KB  init scratch (stageT spans bfragH+this;
                                              //       fragStage aliases this half)
    float    envRaw[2][NWARP][16][12];        // 24KB  staged raw inputs (double-buffered)
    unsigned w1vH[8 * 32 * 4];                // 4KB   W1v fp16 B-frags (1 k16 tile)
    unsigned envP[ROWS][8];                   // 8KB   packed env f16x2 (pairs k0..k15)
    float4   b2w3F[64];                       // 1KB
    float    emsS[8];
    float    eisS[8];
};

// field map: f0=idm1, f1=idm2, f2=idm4, f3=idm5, f4=idm12, f5=idm13, f6..8=mc0..2
#define OFFPACK 0xDC5421u

__global__ void __launch_bounds__(THREADS)
forward_sim_kernel(const float* __restrict__ proj,
                   const float* __restrict__ enc,
                   const float* __restrict__ idm,
                   const float* __restrict__ mc,
                   const float* __restrict__ env_mean,
                   const float* __restrict__ env_var,
                   const float* __restrict__ W1,
                   const float* __restrict__ b1,
                   const float* __restrict__ W2,
                   const float* __restrict__ b2,
                   const float* __restrict__ W3,
                   const float* __restrict__ b3,
                   float* __restrict__ out,
                   int B) {
    extern __shared__ char smem_raw[];
    Smem* s = reinterpret_cast<Smem*>(smem_raw);

    const int tid = threadIdx.x;
    const int lam = tid & 31;
    const int w   = tid >> 5;              // warp owns rows w*16 .. w*16+15
    const int row0 = blockIdx.x * ROWS;

    float* out_disp = out;
    float* out_act  = out + (size_t)B * (T_STEPS + 1);

    // base kept in registers as f16x2 pairs: baseR01[nt] = (d0,d1), baseR23[nt] = (d2,d3)
    unsigned baseR01[16], baseR23[16];

    // ================= INIT =================
    for (int i = tid; i < 64; i += THREADS) {
        int nt = i >> 2, g = i & 3;
        int c0 = nt * 8 + 2 * g;
        s->b2w3F[i] = make_float4(b2[c0], b2[c0 + 1], W3[c0], W3[c0 + 1]);
    }
    if (tid < 8) { s->emsS[tid] = env_mean[tid]; s->eisS[tid] = rsqrtf(env_var[tid]); }
    for (int i = tid; i < ROWS * 8; i += THREADS) ((unsigned*)s->envP)[i] = 0u;

    // W1v (rows 256..266 of W1) -> fp16 B-frags, 1 k16 tile (pad k>=11)
    for (int idx = tid; idx < 8 * 32 * 4; idx += THREADS) {
        int u  = idx & 3;
        int lf = (idx >> 2) & 31;
        int q  = idx >> 7;
        int nt  = 2 * q + (u >> 1);
        int reg = u & 1;
        int k0  = reg * 8 + 2 * (lf & 3);
        int n   = nt * 8 + (lf >> 2);
        float w0 = (k0     < 11) ? W1[(256 + k0)     * 128 + n] : 0.0f;
        float w1 = (k0 + 1 < 11) ? W1[(256 + k0 + 1) * 128 + n] : 0.0f;
        s->w1vH[idx] = cvt2h(w1, w0);
    }

    // --- base = [proj,enc] @ W1[:256] + b1, 4 chunks of 64 rows ---
    // stageT spans bfragH+scratch32 (64KB); fragStage aliases scratch32 (32KB).
    {
        float* stageT    = (float*)s->bfragH;
        float* fragStage = (float*)s->scratch32;
        const int j  = tid & 127;
        const int rh = tid >> 7;                // 0..3 -> rows rh*16..+15 of chunk
        const float b1j = b1[j];
        for (int c = 0; c < 4; c++) {
            __syncthreads();
            for (int idx = tid; idx < 64 * 64; idx += THREADS) {
                int r = idx & 63, kq = idx >> 6;
                int grow = row0 + c * 64 + r;
                float4 v = make_float4(0.f, 0.f, 0.f, 0.f);
                if (grow < B)
                    v = (kq < 32) ? *(const float4*)&proj[(size_t)grow * 128 + kq * 4]
                                  : *(const float4*)&enc [(size_t)grow * 128 + (kq - 32) * 4];
                stageT[(kq * 4 + 0) * 64 + r] = v.x;
                stageT[(kq * 4 + 1) * 64 + r] = v.y;
                stageT[(kq * 4 + 2) * 64 + r] = v.z;
                stageT[(kq * 4 + 3) * 64 + r] = v.w;
            }
            __syncthreads();
            unsigned long long acc[8];
            unsigned long long b1p = pk(b1j, b1j);
#pragma unroll
            for (int p = 0; p < 8; p++) acc[p] = b1p;
#pragma unroll 4
            for (int k = 0; k < 256; k++) {
                float wv = __ldg(&W1[k * 128 + j]);
                unsigned long long wk = pk(wv, wv);
                const unsigned long long* xp =
                    (const unsigned long long*)&stageT[k * 64 + rh * 16];
#pragma unroll
                for (int p = 0; p < 8; p++) ffma2(acc[p], xp[p], wk);
            }
            __syncthreads();   // all stageT reads done before fragStage overwrites its top half
#pragma unroll
            for (int p = 0; p < 8; p++) {
                float2 v = upk(acc[p]);
#pragma unroll
                for (int h = 0; h < 2; h++) {
                    int rcl = rh * 16 + 2 * p + h;      // row within 64-row chunk
                    float val = h ? v.y : v.x;
                    int rr2 = rcl & 15;
                    int lf  = (rr2 & 7) * 4 + ((j & 7) >> 1);
                    int nt  = j >> 3;
                    int d   = ((rr2 >> 3) & 1) * 2 + (j & 1);
                    fragStage[(((rcl >> 4) * 16 + nt) * 32 + lf) * 4 + d] = val;
                }
            }
            __syncthreads();
            if ((w >> 2) == c) {                        // warps 4c..4c+3 own this chunk
#pragma unroll
                for (int nt = 0; nt < 16; nt++) {
                    float4 f = *(const float4*)
                        &fragStage[(((w & 3) * 16 + nt) * 32 + lam) * 4];
                    baseR01[nt] = cvt2h(f.y, f.x);
                    baseR23[nt] = cvt2h(f.w, f.z);
                }
            }
        }
    }
    __syncthreads();

    // --- W2 -> fp16 fragment table (overwrites scratch area) ---
    for (int idx = tid; idx < 8 * 8 * 32 * 4; idx += THREADS) {
        int u  = idx & 3;
        int lf = (idx >> 2) & 31;
        int q  = (idx >> 7) & 7;
        int kt = idx >> 10;
        int nt  = 2 * q + (u >> 1);
        int reg = u & 1;
        int k0  = kt * 16 + reg * 8 + 2 * (lf & 3);
        int n   = nt * 8 + (lf >> 2);
        float w0 = W2[k0 * 128 + n];
        float w1 = W2[(k0 + 1) * 128 + n];
        s->bfragH[idx] = cvt2h(w1, w0);
    }

    // ================= per-thread row ownership =================
    const int ke2 = lam & 3;               // env pair index
    const int qr  = lam >> 2;
    const int er0 = w * 16 + qr;
    const bool own = (lam & 3) < 2;
    const int r2loc = qr + 8 * (lam & 1);  // local row within warp
    const int rrel  = w * 16 + r2loc;
    const int myrow = row0 + rrel;
    const bool rowok = own && (myrow < B);

    float ego_v = 0.f, ego_a = 0.f, ego_x = 0.f, disp = 0.f;

    if (rowok) {
        const float* p0 = idm + (size_t)myrow * T_STEPS * FEAT;
        ego_v = p0[0]; ego_a = p0[11]; ego_x = p0[3];
        out_disp[(size_t)myrow * (T_STEPS + 1)] = 0.0f;
        float p_fv = p0[1], p_mv = p0[2], p_fx = p0[4], p_mx = p0[5];
        float p_fa = p0[12], p_me = p0[13];
        const float* mp = mc + (size_t)myrow * T_STEPS * MDIM;
        float p_m0 = mp[0], p_m1 = mp[1], p_m2 = mp[2];

        // env(t=0) packed as f16x2 pairs
        float ef_dx = p_fx - ego_x;
        float em_dx = (p_mx - ego_x) * p_me + (1.0f - p_me) * DUMMY_DX_;
        float ef_dv = ego_v - p_fv;
        float em_dv = (ego_v - p_mv) * p_me;
        float e0 = (ego_v - s->emsS[0]) * s->eisS[0];
        float e1 = (p_fv  - s->emsS[1]) * s->eisS[1];
        float e2 = (ego_a - s->emsS[2]) * s->eisS[2];
        float e3 = (p_fa  - s->emsS[3]) * s->eisS[3];
        float e4 = (ef_dv - s->emsS[4]) * s->eisS[4];
        float e5 = (ef_dx - s->emsS[5]) * s->eisS[5];
        float e6 = (em_dv - s->emsS[6]) * s->eisS[6];
        float e7 = (em_dx - s->emsS[7]) * s->eisS[7];
        uint4 pa, pb;
        pa.x = cvt2h(e1, e0); pa.y = cvt2h(e3, e2);
        pa.z = cvt2h(e5, e4); pa.w = cvt2h(e7, e6);
        pb.x = cvt2h(p_m1, p_m0); pb.y = cvt2h(0.0f, p_m2);
        pb.z = 0u; pb.w = 0u;
        *(uint4*)&s->envP[rrel][0] = pa;
        *(uint4*)&s->envP[rrel][4] = pb;
    }
    const float b3v = b3[0];

    // --- stage raw inputs for t=1 into envRaw[1] (coalesced flat mapping) ---
    {
        const int tn = (T_STEPS > 1) ? 1 : 0;
#pragma unroll
        for (int k = 0; k < 5; k++) {
            int i = lam + 32 * k;
            if (i < 144) {
                int r = i / 9, f = i - 9 * r;
                int grow = row0 + w * 16 + r;
                float v = 0.0f;
                if (grow < B) {
                    if (f < 6)
                        v = __ldg(idm + ((size_t)grow * T_STEPS + tn) * FEAT
                                  + ((OFFPACK >> (4 * f)) & 0xFu));
                    else
                        v = __ldg(mc + ((size_t)grow * T_STEPS + tn) * MDIM + (f - 6));
                }
                s->envRaw[1][w][r][f] = v;
            }
        }
    }
    __syncthreads();

    // ================= MAIN LOOP (warp-private) =================
    for (int t = 0; t < T_STEPS; t++) {
        // ---- phase B (single-pass fp16 MMA): h1pre = base(regs) + env @ W1v ----
        float D16[16][4];
#pragma unroll
        for (int nt = 0; nt < 16; nt++) {
            float2 b01 = unpk2h(baseR01[nt]);
            float2 b23 = unpk2h(baseR23[nt]);
            D16[nt][0] = b01.x; D16[nt][1] = b01.y;
            D16[nt][2] = b23.x; D16[nt][3] = b23.y;
        }

        unsigned eh0 = s->envP[er0][ke2];
        unsigned eh1 = s->envP[er0 + 8][ke2];
        unsigned eh2 = s->envP[er0][ke2 + 4];
        unsigned eh3 = s->envP[er0 + 8][ke2 + 4];

        // ---- issue coalesced staging LDGs for tn = t+2 (consumed next step) ----
        const int tn = (t + 2 < T_STEPS) ? t + 2 : T_STEPS - 1;
        float sv[5];
#pragma unroll
        for (int k = 0; k < 5; k++) {
            int i = lam + 32 * k;
            sv[k] = 0.0f;
            if (i < 144) {
                int r = i / 9, f = i - 9 * r;
                int grow = row0 + w * 16 + r;
                if (grow < B) {
                    if (f < 6)
                        sv[k] = __ldg(idm + ((size_t)grow * T_STEPS + tn) * FEAT
                                      + ((OFFPACK >> (4 * f)) & 0xFu));
                    else
                        sv[k] = __ldg(mc + ((size_t)grow * T_STEPS + tn) * MDIM + (f - 6));
                }
            }
        }

#pragma unroll
        for (int q = 0; q < 8; q++) {
            uint4 wh = *(const uint4*)&s->w1vH[(q * 32 + lam) * 4];
            mma16816(D16[2*q][0], D16[2*q][1], D16[2*q][2], D16[2*q][3],
                     eh0, eh1, eh2, eh3, wh.x, wh.y);
            mma16816(D16[2*q+1][0], D16[2*q+1][1], D16[2*q+1][2], D16[2*q+1][3],
                     eh0, eh1, eh2, eh3, wh.z, wh.w);
        }

        // ---- leaky + single fp16 round -> phase-C A-frags ----
        unsigned ahi01[16], ahi23[16];
#pragma unroll
        for (int nt = 0; nt < 16; nt++) {
            float v0 = D16[nt][0], v1 = D16[nt][1], v2 = D16[nt][2], v3 = D16[nt][3];
            v0 = fmaxf(v0, ALPHA_ * v0);
            v1 = fmaxf(v1, ALPHA_ * v1);
            v2 = fmaxf(v2, ALPHA_ * v2);
            v3 = fmaxf(v3, ALPHA_ * v3);
            ahi01[nt] = cvt2h(v1, v0);
            ahi23[nt] = cvt2h(v3, v2);
        }

        // ---- phase C: h2 = h1 @ W2 (fp16), 4 N-sweeps, double-buffered W2 loads ----
        float pr0 = 0.0f, pr1 = 0.0f;
#pragma unroll 1
        for (int ns = 0; ns < 4; ns++) {
            float D[4][4];
#pragma unroll
            for (int nl = 0; nl < 4; nl++)
#pragma unroll
                for (int d = 0; d < 4; d++) D[nl][d] = 0.0f;

            uint4 nb0 = *(const uint4*)&s->bfragH[((2 * ns) * 32 + lam) * 4];
            uint4 nb1 = *(const uint4*)&s->bfragH[((2 * ns + 1) * 32 + lam) * 4];
#pragma unroll
            for (int kt = 0; kt < 8; kt++) {
                uint4 cb0 = nb0, cb1 = nb1;
                if (kt < 7) {
                    nb0 = *(const uint4*)&s->bfragH[(((kt + 1) * 8 + 2 * ns) * 32 + lam) * 4];
                    nb1 = *(const uint4*)&s->bfragH[(((kt + 1) * 8 + 2 * ns + 1) * 32 + lam) * 4];
                }
                unsigned a0 = ahi01[2 * kt],     a1 = ahi23[2 * kt];
                unsigned a2 = ahi01[2 * kt + 1], a3 = ahi23[2 * kt + 1];
                mma16816(D[0][0], D[0][1], D[0][2], D[0][3], a0, a1, a2, a3, cb0.x, cb0.y);
                mma16816(D[1][0], D[1][1], D[1][2], D[1][3], a0, a1, a2, a3, cb0.z, cb0.w);
                mma16816(D[2][0], D[2][1], D[2][2], D[2][3], a0, a1, a2, a3, cb1.x, cb1.y);
                mma16816(D[3][0], D[3][1], D[3][2], D[3][3], a0, a1, a2, a3, cb1.z, cb1.w);
            }
#pragma unroll
            for (int nl = 0; nl < 4; nl++) {
                int nt = 4 * ns + nl;
                float4 bw = s->b2w3F[nt * 4 + (lam & 3)];
                float v0 = D[nl][0] + bw.x;
                float v1 = D[nl][1] + bw.y;
                float v2 = D[nl][2] + bw.x;
                float v3 = D[nl][3] + bw.y;
                v0 = fmaxf(v0, ALPHA_ * v0);
                v1 = fmaxf(v1, ALPHA_ * v1);
                v2 = fmaxf(v2, ALPHA_ * v2);
                v3 = fmaxf(v3, ALPHA_ * v3);
                pr0 = fmaf(v0, bw.z, fmaf(v1, bw.w, pr0));
                pr1 = fmaf(v2, bw.z, fmaf(v3, bw.w, pr1));
            }
        }

        // ---- quad reduce over n-columns ----
        pr0 += __shfl_xor_sync(0xffffffffu, pr0, 1);
        pr0 += __shfl_xor_sync(0xffffffffu, pr0, 2);
        pr1 += __shfl_xor_sync(0xffffffffu, pr1, 1);
        pr1 += __shfl_xor_sync(0xffffffffu, pr1, 2);

        __syncwarp();   // envP reads for step t done before rewrite

        // ---- state update + outputs + env(t+1) from staged buffer ----
        if (rowok) {
            float a = ((lam & 1) ? pr1 : pr0) + b3v;
            float move = ego_v * DT_ + 0.5f * a * DT_ * DT_;
            disp  += move;
            ego_x += move;
            ego_v += a * DT_;
            ego_a  = a;
            out_act [(size_t)myrow * T_STEPS + t]           = a;
            out_disp[(size_t)myrow * (T_STEPS + 1) + t + 1] = disp;

            if (t + 1 < T_STEPS) {
                const float* rw = &s->envRaw[(t + 1) & 1][w][r2loc][0];
                float4 A  = *(const float4*)rw;        // idm1, idm2, idm4, idm5
                float4 Bv = *(const float4*)(rw + 4);  // idm12, idm13, mc0, mc1
                float m2v = rw[8];                     // mc2
                float p_fv = A.x, p_mv = A.y, p_fx = A.z, p_mx = A.w;
                float p_fa = Bv.x, p_me = Bv.y;

                float ef_dx = p_fx - ego_x;
                float em_dx = (p_mx - ego_x) * p_me + (1.0f - p_me) * DUMMY_DX_;
                float ef_dv = ego_v - p_fv;
                float em_dv = (ego_v - p_mv) * p_me;
                float e0 = (ego_v - s->emsS[0]) * s->eisS[0];
                float e1 = (p_fv  - s->emsS[1]) * s->eisS[1];
                float e2 = (ego_a - s->emsS[2]) * s->eisS[2];
                float e3 = (p_fa  - s->emsS[3]) * s->eisS[3];
                float e4 = (ef_dv - s->emsS[4]) * s->eisS[4];
                float e5 = (ef_dx - s->emsS[5]) * s->eisS[5];
                float e6 = (em_dv - s->emsS[6]) * s->eisS[6];
                float e7 = (em_dx - s->emsS[7]) * s->eisS[7];
                uint4 pa, pb;
                pa.x = cvt2h(e1, e0); pa.y = cvt2h(e3, e2);
                pa.z = cvt2h(e5, e4); pa.w = cvt2h(e7, e6);
                pb.x = cvt2h(Bv.w, Bv.z); pb.y = cvt2h(0.0f, m2v);
                pb.z = 0u; pb.w = 0u;
                *(uint4*)&s->envP[rrel][0] = pa;
                *(uint4*)&s->envP[rrel][4] = pb;
            }
        }

        // ---- store staged loads for tn = t+2 into envRaw[t&1] ----
#pragma unroll
        for (int k = 0; k < 5; k++) {
            int i = lam + 32 * k;
            if (i < 144) {
                int r = i / 9, f = i - 9 * r;
                s->envRaw[t & 1][w][r][f] = sv[k];
            }
        }
        __syncwarp();   // env + staging writes visible before next iteration's reads
    }
}

extern "C" void kernel_launch(void* const* d_in, const int* in_sizes, int n_in,
                              void* d_out, int out_size) {
    const float* proj     = (const float*)d_in[0];
    const float* enc      = (const float*)d_in[1];
    const float* idm      = (const float*)d_in[2];
    const float* mc       = (const float*)d_in[3];
    const float* env_mean = (const float*)d_in[4];
    const float* env_var  = (const float*)d_in[5];
    const float* W1       = (const float*)d_in[6];
    const float* b1       = (const float*)d_in[7];
    const float* W2       = (const float*)d_in[8];
    const float* b2       = (const float*)d_in[9];
    const float* W3       = (const float*)d_in[10];
    const float* b3       = (const float*)d_in[11];
    float* out = (float*)d_out;

    int B = in_sizes[0] / 128;

    int smem = (int)sizeof(Smem);
    cudaFuncSetAttribute(forward_sim_kernel,
                         cudaFuncAttributeMaxDynamicSharedMemorySize, smem);

    dim3 grid((B + ROWS - 1) / ROWS);
    forward_sim_kernel<<<grid, THREADS, smem>>>(
        proj, enc, idm, mc, env_mean, env_var,
        W1, b1, W2, b2, W3, b3, out, B);
}

// round 16
// speedup vs baseline: 1.0291x; 1.0291x over previous
#include <cuda_runtime.h>
#include <cuda_fp16.h>
#include <cstdint>

#define T_STEPS 50
#define FEAT    14
#define MDIM    3
#define DT_     0.1f
#define ALPHA_  0.3f
#define DUMMY_DX_ 50.0f
#define ROWS    256
#define THREADS 512
#define NWARP   16

// ---------------- helpers ----------------
__device__ __forceinline__ void ffma2(unsigned long long &acc,
                                      unsigned long long a, unsigned long long b) {
    asm("fma.rn.f32x2 %0, %1, %2, %0;" : "+l"(acc) : "l"(a), "l"(b));
}
__device__ __forceinline__ unsigned long long pk(float lo, float hi) {
    unsigned long long r;
    asm("mov.b64 %0, {%1, %2};" : "=l"(r) : "f"(lo), "f"(hi));
    return r;
}
__device__ __forceinline__ float2 upk(unsigned long long v) {
    float2 f;
    asm("mov.b64 {%0, %1}, %2;" : "=f"(f.x), "=f"(f.y) : "l"(v));
    return f;
}
// packed f16x2: high half = cvt(a), low half = cvt(b)
__device__ __forceinline__ unsigned cvt2h(float hi, float lo) {
    unsigned r;
    asm("cvt.rn.f16x2.f32 %0, %1, %2;" : "=r"(r) : "f"(hi), "f"(lo));
    return r;
}
__device__ __forceinline__ float2 unpk2h(unsigned u) {
    __half2 h = *reinterpret_cast<__half2*>(&u);
    return __half22float2(h);          // .x = lo, .y = hi
}

__device__ __forceinline__ void mma16816(float &d0, float &d1, float &d2, float &d3,
                                         unsigned a0, unsigned a1, unsigned a2, unsigned a3,
                                         unsigned b0, unsigned b1) {
    asm("mma.sync.aligned.m16n8k16.row.col.f32.f16.f16.f32 "
        "{%0,%1,%2,%3}, {%4,%5,%6,%7}, {%8,%9}, {%0,%1,%2,%3};"
        : "+f"(d0), "+f"(d1), "+f"(d2), "+f"(d3)
        : "r"(a0), "r"(a1), "r"(a2), "r"(a3), "r"(b0), "r"(b1));
}

// ---------------- smem (~78KB) ----------------
struct __align__(16) Smem {
    unsigned bfragH[8 * 8 * 32 * 4];          // 32KB  W2 fp16 frags [((kt*8+q)*32+lam)*4+u]
    unsigned scratch32[8 * 8 * 32 * 4];       // 32KB  init scratch (stageT spans bfragH+this;
                                              //       fragStage aliases this half)
    unsigned w1vH[8 * 32 * 4];                // 4KB   W1v fp16 B-frags (1 k16 tile)
    unsigned envP[ROWS][8];                   // 8KB   packed env f16x2 (pairs k0..k15)
    float4   b2w3F[64];                       // 1KB
    float    emsS[8];
    float    eisS[8];
};

__global__ void __launch_bounds__(THREADS)
forward_sim_kernel(const float* __restrict__ proj,
                   const float* __restrict__ enc,
                   const float* __restrict__ idm,
                   const float* __restrict__ mc,
                   const float* __restrict__ env_mean,
                   const float* __restrict__ env_var,
                   const float* __restrict__ W1,
                   const float* __restrict__ b1,
                   const float* __restrict__ W2,
                   const float* __restrict__ b2,
                   const float* __restrict__ W3,
                   const float* __restrict__ b3,
                   float* __restrict__ out,
                   int B) {
    extern __shared__ char smem_raw[];
    Smem* s = reinterpret_cast<Smem*>(smem_raw);

    const int tid = threadIdx.x;
    const int lam = tid & 31;
    const int w   = tid >> 5;              // warp owns rows w*16 .. w*16+15
    const int row0 = blockIdx.x * ROWS;

    float* out_disp = out;
    float* out_act  = out + (size_t)B * (T_STEPS + 1);

    // base kept in registers as f16x2 pairs: baseR01[nt] = (d0,d1), baseR23[nt] = (d2,d3)
    unsigned baseR01[16], baseR23[16];

    // ================= INIT =================
    for (int i = tid; i < 64; i += THREADS) {
        int nt = i >> 2, g = i & 3;
        int c0 = nt * 8 + 2 * g;
        s->b2w3F[i] = make_float4(b2[c0], b2[c0 + 1], W3[c0], W3[c0 + 1]);
    }
    if (tid < 8) { s->emsS[tid] = env_mean[tid]; s->eisS[tid] = rsqrtf(env_var[tid]); }
    for (int i = tid; i < ROWS * 8; i += THREADS) ((unsigned*)s->envP)[i] = 0u;

    // W1v (rows 256..266 of W1) -> fp16 B-frags, 1 k16 tile (pad k>=11)
    for (int idx = tid; idx < 8 * 32 * 4; idx += THREADS) {
        int u  = idx & 3;
        int lf = (idx >> 2) & 31;
        int q  = idx >> 7;
        int nt  = 2 * q + (u >> 1);
        int reg = u & 1;
        int k0  = reg * 8 + 2 * (lf & 3);
        int n   = nt * 8 + (lf >> 2);
        float w0 = (k0     < 11) ? W1[(256 + k0)     * 128 + n] : 0.0f;
        float w1 = (k0 + 1 < 11) ? W1[(256 + k0 + 1) * 128 + n] : 0.0f;
        s->w1vH[idx] = cvt2h(w1, w0);
    }

    // --- base = [proj,enc] @ W1[:256] + b1, 4 chunks of 64 rows ---
    // stageT spans bfragH+scratch32 (64KB); fragStage aliases scratch32 (32KB).
    {
        float* stageT    = (float*)s->bfragH;
        float* fragStage = (float*)s->scratch32;
        const int j  = tid & 127;
        const int rh = tid >> 7;                // 0..3 -> rows rh*16..+15 of chunk
        const float b1j = b1[j];
        for (int c = 0; c < 4; c++) {
            __syncthreads();
            for (int idx = tid; idx < 64 * 64; idx += THREADS) {
                int r = idx & 63, kq = idx >> 6;
                int grow = row0 + c * 64 + r;
                float4 v = make_float4(0.f, 0.f, 0.f, 0.f);
                if (grow < B)
                    v = (kq < 32) ? *(const float4*)&proj[(size_t)grow * 128 + kq * 4]
                                  : *(const float4*)&enc [(size_t)grow * 128 + (kq - 32) * 4];
                stageT[(kq * 4 + 0) * 64 + r] = v.x;
                stageT[(kq * 4 + 1) * 64 + r] = v.y;
                stageT[(kq * 4 + 2) * 64 + r] = v.z;
                stageT[(kq * 4 + 3) * 64 + r] = v.w;
            }
            __syncthreads();
            unsigned long long acc[8];
            unsigned long long b1p = pk(b1j, b1j);
#pragma unroll
            for (int p = 0; p < 8; p++) acc[p] = b1p;
#pragma unroll 4
            for (int k = 0; k < 256; k++) {
                float wv = __ldg(&W1[k * 128 + j]);
                unsigned long long wk = pk(wv, wv);
                const unsigned long long* xp =
                    (const unsigned long long*)&stageT[k * 64 + rh * 16];
#pragma unroll
                for (int p = 0; p < 8; p++) ffma2(acc[p], xp[p], wk);
            }
            __syncthreads();   // all stageT reads done before fragStage overwrites its top half
#pragma unroll
            for (int p = 0; p < 8; p++) {
                float2 v = upk(acc[p]);
#pragma unroll
                for (int h = 0; h < 2; h++) {
                    int rcl = rh * 16 + 2 * p + h;      // row within 64-row chunk
                    float val = h ? v.y : v.x;
                    int rr2 = rcl & 15;
                    int lf  = (rr2 & 7) * 4 + ((j & 7) >> 1);
                    int nt  = j >> 3;
                    int d   = ((rr2 >> 3) & 1) * 2 + (j & 1);
                    fragStage[(((rcl >> 4) * 16 + nt) * 32 + lf) * 4 + d] = val;
                }
            }
            __syncthreads();
            if ((w >> 2) == c) {                        // warps 4c..4c+3 own this chunk
#pragma unroll
                for (int nt = 0; nt < 16; nt++) {
                    float4 f = *(const float4*)
                        &fragStage[(((w & 3) * 16 + nt) * 32 + lam) * 4];
                    baseR01[nt] = cvt2h(f.y, f.x);
                    baseR23[nt] = cvt2h(f.w, f.z);
                }
            }
        }
    }
    __syncthreads();

    // --- W2 -> fp16 fragment table (overwrites scratch area) ---
    for (int idx = tid; idx < 8 * 8 * 32 * 4; idx += THREADS) {
        int u  = idx & 3;
        int lf = (idx >> 2) & 31;
        int q  = (idx >> 7) & 7;
        int kt = idx >> 10;
        int nt  = 2 * q + (u >> 1);
        int reg = u & 1;
        int k0  = kt * 16 + reg * 8 + 2 * (lf & 3);
        int n   = nt * 8 + (lf >> 2);
        float w0 = W2[k0 * 128 + n];
        float w1 = W2[(k0 + 1) * 128 + n];
        s->bfragH[idx] = cvt2h(w1, w0);
    }
    __syncthreads();

    // ================= per-thread row ownership =================
    const int ke2 = lam & 3;               // env pair index
    const int qr  = lam >> 2;
    const int er0 = w * 16 + qr;
    const bool own = (lam & 3) < 2;
    const int rrel  = w * 16 + qr + 8 * (lam & 1);
    const int myrow = row0 + rrel;
    const bool rowok = own && (myrow < B);

    float ego_v = 0.f, ego_a = 0.f, ego_x = 0.f, disp = 0.f;
    float p_fv = 0.f, p_mv = 0.f, p_fx = 0.f, p_mx = 0.f, p_fa = 0.f, p_me = 0.f;
    float p_m0 = 0.f, p_m1 = 0.f, p_m2 = 0.f;

    if (rowok) {
        const float* p0 = idm + (size_t)myrow * T_STEPS * FEAT;
        ego_v = p0[0]; ego_a = p0[11]; ego_x = p0[3];
        out_disp[(size_t)myrow * (T_STEPS + 1)] = 0.0f;
        p_fv = p0[1]; p_mv = p0[2]; p_fx = p0[4]; p_mx = p0[5];
        p_fa = p0[12]; p_me = p0[13];
        const float* mp = mc + (size_t)myrow * T_STEPS * MDIM;
        p_m0 = mp[0]; p_m1 = mp[1]; p_m2 = mp[2];

        // env(t=0) packed as f16x2 pairs
        float ef_dx = p_fx - ego_x;
        float em_dx = (p_mx - ego_x) * p_me + (1.0f - p_me) * DUMMY_DX_;
        float ef_dv = ego_v - p_fv;
        float em_dv = (ego_v - p_mv) * p_me;
        float e0 = (ego_v - s->emsS[0]) * s->eisS[0];
        float e1 = (p_fv  - s->emsS[1]) * s->eisS[1];
        float e2 = (ego_a - s->emsS[2]) * s->eisS[2];
        float e3 = (p_fa  - s->emsS[3]) * s->eisS[3];
        float e4 = (ef_dv - s->emsS[4]) * s->eisS[4];
        float e5 = (ef_dx - s->emsS[5]) * s->eisS[5];
        float e6 = (em_dv - s->emsS[6]) * s->eisS[6];
        float e7 = (em_dx - s->emsS[7]) * s->eisS[7];
        uint4 pa, pb;
        pa.x = cvt2h(e1, e0); pa.y = cvt2h(e3, e2);
        pa.z = cvt2h(e5, e4); pa.w = cvt2h(e7, e6);
        pb.x = cvt2h(p_m1, p_m0); pb.y = cvt2h(0.0f, p_m2);
        pb.z = 0u; pb.w = 0u;
        *(uint4*)&s->envP[rrel][0] = pa;
        *(uint4*)&s->envP[rrel][4] = pb;

        const float* ip = idm + ((size_t)myrow * T_STEPS + 1) * FEAT;
        p_fv = ip[1]; p_mv = ip[2]; p_fx = ip[4]; p_mx = ip[5];
        p_fa = ip[12]; p_me = ip[13];
        const float* mp2 = mc + ((size_t)myrow * T_STEPS + 1) * MDIM;
        p_m0 = mp2[0]; p_m1 = mp2[1]; p_m2 = mp2[2];
    }
    const float b3v = b3[0];
    __syncthreads();

    // ================= MAIN LOOP (warp-private) =================
    for (int t = 0; t < T_STEPS; t++) {
        // ---- phase B (single-pass fp16 MMA): h1pre = base(regs) + env @ W1v ----
        float D16[16][4];
#pragma unroll
        for (int nt = 0; nt < 16; nt++) {
            float2 b01 = unpk2h(baseR01[nt]);
            float2 b23 = unpk2h(baseR23[nt]);
            D16[nt][0] = b01.x; D16[nt][1] = b01.y;
            D16[nt][2] = b23.x; D16[nt][3] = b23.y;
        }

        unsigned eh0 = s->envP[er0][ke2];
        unsigned eh1 = s->envP[er0 + 8][ke2];
        unsigned eh2 = s->envP[er0][ke2 + 4];
        unsigned eh3 = s->envP[er0 + 8][ke2 + 4];

#pragma unroll
        for (int q = 0; q < 8; q++) {
            uint4 wh = *(const uint4*)&s->w1vH[(q * 32 + lam) * 4];
            mma16816(D16[2*q][0], D16[2*q][1], D16[2*q][2], D16[2*q][3],
                     eh0, eh1, eh2, eh3, wh.x, wh.y);
            mma16816(D16[2*q+1][0], D16[2*q+1][1], D16[2*q+1][2], D16[2*q+1][3],
                     eh0, eh1, eh2, eh3, wh.z, wh.w);
        }

        // ---- leaky + single fp16 round -> phase-C A-frags ----
        unsigned ahi01[16], ahi23[16];
#pragma unroll
        for (int nt = 0; nt < 16; nt++) {
            float v0 = D16[nt][0], v1 = D16[nt][1], v2 = D16[nt][2], v3 = D16[nt][3];
            v0 = fmaxf(v0, ALPHA_ * v0);
            v1 = fmaxf(v1, ALPHA_ * v1);
            v2 = fmaxf(v2, ALPHA_ * v2);
            v3 = fmaxf(v3, ALPHA_ * v3);
            ahi01[nt] = cvt2h(v1, v0);
            ahi23[nt] = cvt2h(v3, v2);
        }

        // ---- phase C: h2 = h1 @ W2 (fp16), fully unrolled 4 N-sweeps ----
        float pr0 = 0.0f, pr1 = 0.0f;
#pragma unroll
        for (int ns = 0; ns < 4; ns++) {
            float D[4][4];
#pragma unroll
            for (int nl = 0; nl < 4; nl++)
#pragma unroll
                for (int d = 0; d < 4; d++) D[nl][d] = 0.0f;

#pragma unroll
            for (int kt = 0; kt < 8; kt++) {
                const uint4 cb0 = *(const uint4*)&s->bfragH[((kt * 8 + 2 * ns) * 32 + lam) * 4];
                const uint4 cb1 = *(const uint4*)&s->bfragH[((kt * 8 + 2 * ns + 1) * 32 + lam) * 4];
                unsigned a0 = ahi01[2 * kt],     a1 = ahi23[2 * kt];
                unsigned a2 = ahi01[2 * kt + 1], a3 = ahi23[2 * kt + 1];
                mma16816(D[0][0], D[0][1], D[0][2], D[0][3], a0, a1, a2, a3, cb0.x, cb0.y);
                mma16816(D[1][0], D[1][1], D[1][2], D[1][3], a0, a1, a2, a3, cb0.z, cb0.w);
                mma16816(D[2][0], D[2][1], D[2][2], D[2][3], a0, a1, a2, a3, cb1.x, cb1.y);
                mma16816(D[3][0], D[3][1], D[3][2], D[3][3], a0, a1, a2, a3, cb1.z, cb1.w);
            }
#pragma unroll
            for (int nl = 0; nl < 4; nl++) {
                int nt = 4 * ns + nl;
                float4 bw = s->b2w3F[nt * 4 + (lam & 3)];
                float v0 = D[nl][0] + bw.x;
                float v1 = D[nl][1] + bw.y;
                float v2 = D[nl][2] + bw.x;
                float v3 = D[nl][3] + bw.y;
                v0 = fmaxf(v0, ALPHA_ * v0);
                v1 = fmaxf(v1, ALPHA_ * v1);
                v2 = fmaxf(v2, ALPHA_ * v2);
                v3 = fmaxf(v3, ALPHA_ * v3);
                pr0 = fmaf(v0, bw.z, fmaf(v1, bw.w, pr0));
                pr1 = fmaf(v2, bw.z, fmaf(v3, bw.w, pr1));
            }
        }

        // ---- quad reduce over n-columns ----
        pr0 += __shfl_xor_sync(0xffffffffu, pr0, 1);
        pr0 += __shfl_xor_sync(0xffffffffu, pr0, 2);
        pr1 += __shfl_xor_sync(0xffffffffu, pr1, 1);
        pr1 += __shfl_xor_sync(0xffffffffu, pr1, 2);

        __syncwarp();   // envP reads for step t done before rewrite

        // ---- state update + outputs + env(t+1) + prefetch(t+2) ----
        if (rowok) {
            float a = ((lam & 1) ? pr1 : pr0) + b3v;
            float move = ego_v * DT_ + 0.5f * a * DT_ * DT_;
            disp  += move;
            ego_x += move;
            ego_v += a * DT_;
            ego_a  = a;
            out_act [(size_t)myrow * T_STEPS + t]           = a;
            out_disp[(size_t)myrow * (T_STEPS + 1) + t + 1] = disp;

            if (t + 1 < T_STEPS) {
                float ef_dx = p_fx - ego_x;
                float em_dx = (p_mx - ego_x) * p_me + (1.0f - p_me) * DUMMY_DX_;
                float ef_dv = ego_v - p_fv;
                float em_dv = (ego_v - p_mv) * p_me;
                float e0 = (ego_v - s->emsS[0]) * s->eisS[0];
                float e1 = (p_fv  - s->emsS[1]) * s->eisS[1];
                float e2 = (ego_a - s->emsS[2]) * s->eisS[2];
                float e3 = (p_fa  - s->emsS[3]) * s->eisS[3];
                float e4 = (ef_dv - s->emsS[4]) * s->eisS[4];
                float e5 = (ef_dx - s->emsS[5]) * s->eisS[5];
                float e6 = (em_dv - s->emsS[6]) * s->eisS[6];
                float e7 = (em_dx - s->emsS[7]) * s->eisS[7];
                uint4 pa, pb;
                pa.x = cvt2h(e1, e0); pa.y = cvt2h(e3, e2);
                pa.z = cvt2h(e5, e4); pa.w = cvt2h(e7, e6);
                pb.x = cvt2h(p_m1, p_m0); pb.y = cvt2h(0.0f, p_m2);
                pb.z = 0u; pb.w = 0u;
                *(uint4*)&s->envP[rrel][0] = pa;
                *(uint4*)&s->envP[rrel][4] = pb;

                int tn = (t + 2 < T_STEPS) ? t + 2 : T_STEPS - 1;
                const float* ip = idm + ((size_t)myrow * T_STEPS + tn) * FEAT;
                p_fv = ip[1]; p_mv = ip[2]; p_fx = ip[4]; p_mx = ip[5];
                p_fa = ip[12]; p_me = ip[13];
                const float* mp = mc + ((size_t)myrow * T_STEPS + tn) * MDIM;
                p_m0 = mp[0]; p_m1 = mp[1]; p_m2 = mp[2];
            }
        }
        __syncwarp();   // env writes visible before next iteration's reads
    }
}

extern "C" void kernel_launch(void* const* d_in, const int* in_sizes, int n_in,
                              void* d_out, int out_size) {
    const float* proj     = (const float*)d_in[0];
    const float* enc      = (const float*)d_in[1];
    const float* idm      = (const float*)d_in[2];
    const float* mc       = (const float*)d_in[3];
    const float* env_mean = (const float*)d_in[4];
    const float* env_var  = (const float*)d_in[5];
    const float* W1       = (const float*)d_in[6];
    const float* b1       = (const float*)d_in[7];
    const float* W2       = (const float*)d_in[8];
    const float* b2       = (const float*)d_in[9];
    const float* W3       = (const float*)d_in[10];
    const float* b3       = (const float*)d_in[11];
    float* out = (float*)d_out;

    int B = in_sizes[0] / 128;

    int smem = (int)sizeof(Smem);
    cudaFuncSetAttribute(forward_sim_kernel,
                         cudaFuncAttributeMaxDynamicSharedMemorySize, smem);

    dim3 grid((B + ROWS - 1) / ROWS);
    forward_sim_kernel<<<grid, THREADS, smem>>>(
        proj, enc, idm, mc, env_mean, env_var,
        W1, b1, W2, b2, W3, b3, out, B);
}

// round 17
// speedup vs baseline: 1.0532x; 1.0234x over previous
#include <cuda_runtime.h>
#include <cuda_fp16.h>
#include <cstdint>

#define T_STEPS 50
#define FEAT    14
#define MDIM    3
#define DT_     0.1f
#define ALPHA_  0.3f
#define DUMMY_DX_ 50.0f
#define ROWS    256
#define THREADS 512
#define NWARP   16

// ---------------- helpers ----------------
__device__ __forceinline__ void ffma2(unsigned long long &acc,
                                      unsigned long long a, unsigned long long b) {
    asm("fma.rn.f32x2 %0, %1, %2, %0;" : "+l"(acc) : "l"(a), "l"(b));
}
__device__ __forceinline__ unsigned long long pk(float lo, float hi) {
    unsigned long long r;
    asm("mov.b64 %0, {%1, %2};" : "=l"(r) : "f"(lo), "f"(hi));
    return r;
}
__device__ __forceinline__ float2 upk(unsigned long long v) {
    float2 f;
    asm("mov.b64 {%0, %1}, %2;" : "=f"(f.x), "=f"(f.y) : "l"(v));
    return f;
}
// packed f16x2: high half = cvt(a), low half = cvt(b)
__device__ __forceinline__ unsigned cvt2h(float hi, float lo) {
    unsigned r;
    asm("cvt.rn.f16x2.f32 %0, %1, %2;" : "=r"(r) : "f"(hi), "f"(lo));
    return r;
}
__device__ __forceinline__ float2 unpk2h(unsigned u) {
    __half2 h = *reinterpret_cast<__half2*>(&u);
    return __half22float2(h);          // .x = lo, .y = hi
}

__device__ __forceinline__ void mma16816(float &d0, float &d1, float &d2, float &d3,
                                         unsigned a0, unsigned a1, unsigned a2, unsigned a3,
                                         unsigned b0, unsigned b1) {
    asm("mma.sync.aligned.m16n8k16.row.col.f32.f16.f16.f32 "
        "{%0,%1,%2,%3}, {%4,%5,%6,%7}, {%8,%9}, {%0,%1,%2,%3};"
        : "+f"(d0), "+f"(d1), "+f"(d2), "+f"(d3)
        : "r"(a0), "r"(a1), "r"(a2), "r"(a3), "r"(b0), "r"(b1));
}

// ---------------- smem (~78KB) ----------------
struct __align__(16) Smem {
    unsigned bfragH[8 * 8 * 32 * 4];          // 32KB  W2 fp16 frags [((kt*8+q)*32+lam)*4+u]
    unsigned scratch32[8 * 8 * 32 * 4];       // 32KB  init scratch (stageT spans bfragH+this;
                                              //       fragStage aliases this half)
    unsigned w1vH[8 * 32 * 4];                // 4KB   W1v fp16 B-frags (1 k16 tile)
    unsigned envP[ROWS][8];                   // 8KB   packed env f16x2 (pairs k0..k15)
    float4   b2w3F[64];                       // 1KB
    float    emsS[8];
    float    eisS[8];
};

__global__ void __launch_bounds__(THREADS)
forward_sim_kernel(const float* __restrict__ proj,
                   const float* __restrict__ enc,
                   const float* __restrict__ idm,
                   const float* __restrict__ mc,
                   const float* __restrict__ env_mean,
                   const float* __restrict__ env_var,
                   const float* __restrict__ W1,
                   const float* __restrict__ b1,
                   const float* __restrict__ W2,
                   const float* __restrict__ b2,
                   const float* __restrict__ W3,
                   const float* __restrict__ b3,
                   float* __restrict__ out,
                   int B) {
    extern __shared__ char smem_raw[];
    Smem* s = reinterpret_cast<Smem*>(smem_raw);

    const int tid = threadIdx.x;
    const int lam = tid & 31;
    const int w   = tid >> 5;              // warp owns rows w*16 .. w*16+15
    const int row0 = blockIdx.x * ROWS;

    float* out_disp = out;
    float* out_act  = out + (size_t)B * (T_STEPS + 1);

    // base kept in registers as f16x2 pairs: baseR01[nt] = (d0,d1), baseR23[nt] = (d2,d3)
    unsigned baseR01[16], baseR23[16];

    // ================= INIT =================
    for (int i = tid; i < 64; i += THREADS) {
        int nt = i >> 2, g = i & 3;
        int c0 = nt * 8 + 2 * g;
        s->b2w3F[i] = make_float4(b2[c0], b2[c0 + 1], W3[c0], W3[c0 + 1]);
    }
    if (tid < 8) { s->emsS[tid] = env_mean[tid]; s->eisS[tid] = rsqrtf(env_var[tid]); }
    for (int i = tid; i < ROWS * 8; i += THREADS) ((unsigned*)s->envP)[i] = 0u;

    // W1v (rows 256..266 of W1) -> fp16 B-frags, 1 k16 tile (pad k>=11)
    for (int idx = tid; idx < 8 * 32 * 4; idx += THREADS) {
        int u  = idx & 3;
        int lf = (idx >> 2) & 31;
        int q  = idx >> 7;
        int nt  = 2 * q + (u >> 1);
        int reg = u & 1;
        int k0  = reg * 8 + 2 * (lf & 3);
        int n   = nt * 8 + (lf >> 2);
        float w0 = (k0     < 11) ? W1[(256 + k0)     * 128 + n] : 0.0f;
        float w1 = (k0 + 1 < 11) ? W1[(256 + k0 + 1) * 128 + n] : 0.0f;
        s->w1vH[idx] = cvt2h(w1, w0);
    }

    // --- base = [proj,enc] @ W1[:256] + b1, 4 chunks of 64 rows ---
    // stageT spans bfragH+scratch32 (64KB); fragStage aliases scratch32 (32KB).
    {
        float* stageT    = (float*)s->bfragH;
        float* fragStage = (float*)s->scratch32;
        const int j  = tid & 127;
        const int rh = tid >> 7;                // 0..3 -> rows rh*16..+15 of chunk
        const float b1j = b1[j];
        for (int c = 0; c < 4; c++) {
            __syncthreads();
            for (int idx = tid; idx < 64 * 64; idx += THREADS) {
                int r = idx & 63, kq = idx >> 6;
                int grow = row0 + c * 64 + r;
                float4 v = make_float4(0.f, 0.f, 0.f, 0.f);
                if (grow < B)
                    v = (kq < 32) ? *(const float4*)&proj[(size_t)grow * 128 + kq * 4]
                                  : *(const float4*)&enc [(size_t)grow * 128 + (kq - 32) * 4];
                stageT[(kq * 4 + 0) * 64 + r] = v.x;
                stageT[(kq * 4 + 1) * 64 + r] = v.y;
                stageT[(kq * 4 + 2) * 64 + r] = v.z;
                stageT[(kq * 4 + 3) * 64 + r] = v.w;
            }
            __syncthreads();
            unsigned long long acc[8];
            unsigned long long b1p = pk(b1j, b1j);
#pragma unroll
            for (int p = 0; p < 8; p++) acc[p] = b1p;
#pragma unroll 4
            for (int k = 0; k < 256; k++) {
                float wv = __ldg(&W1[k * 128 + j]);
                unsigned long long wk = pk(wv, wv);
                const unsigned long long* xp =
                    (const unsigned long long*)&stageT[k * 64 + rh * 16];
#pragma unroll
                for (int p = 0; p < 8; p++) ffma2(acc[p], xp[p], wk);
            }
            __syncthreads();   // all stageT reads done before fragStage overwrites its top half
#pragma unroll
            for (int p = 0; p < 8; p++) {
                float2 v = upk(acc[p]);
#pragma unroll
                for (int h = 0; h < 2; h++) {
                    int rcl = rh * 16 + 2 * p + h;      // row within 64-row chunk
                    float val = h ? v.y : v.x;
                    int rr2 = rcl & 15;
                    int lf  = (rr2 & 7) * 4 + ((j & 7) >> 1);
                    int nt  = j >> 3;
                    int d   = ((rr2 >> 3) & 1) * 2 + (j & 1);
                    fragStage[(((rcl >> 4) * 16 + nt) * 32 + lf) * 4 + d] = val;
                }
            }
            __syncthreads();
            if ((w >> 2) == c) {                        // warps 4c..4c+3 own this chunk
#pragma unroll
                for (int nt = 0; nt < 16; nt++) {
                    float4 f = *(const float4*)
                        &fragStage[(((w & 3) * 16 + nt) * 32 + lam) * 4];
                    baseR01[nt] = cvt2h(f.y, f.x);
                    baseR23[nt] = cvt2h(f.w, f.z);
                }
            }
        }
    }
    __syncthreads();

    // --- W2 -> fp16 fragment table (overwrites scratch area) ---
    for (int idx = tid; idx < 8 * 8 * 32 * 4; idx += THREADS) {
        int u  = idx & 3;
        int lf = (idx >> 2) & 31;
        int q  = (idx >> 7) & 7;
        int kt = idx >> 10;
        int nt  = 2 * q + (u >> 1);
        int reg = u & 1;
        int k0  = kt * 16 + reg * 8 + 2 * (lf & 3);
        int n   = nt * 8 + (lf >> 2);
        float w0 = W2[k0 * 128 + n];
        float w1 = W2[(k0 + 1) * 128 + n];
        s->bfragH[idx] = cvt2h(w1, w0);
    }
    __syncthreads();

    // ================= per-thread row ownership =================
    const int ke2 = lam & 3;               // env pair index
    const int qr  = lam >> 2;
    const int er0 = w * 16 + qr;
    const bool own = (lam & 3) < 2;
    const int rrel  = w * 16 + qr + 8 * (lam & 1);
    const int myrow = row0 + rrel;
    const bool rowok = own && (myrow < B);

    float ego_v = 0.f, ego_a = 0.f, ego_x = 0.f, disp = 0.f;
    float p_fv = 0.f, p_mv = 0.f, p_fx = 0.f, p_mx = 0.f, p_fa = 0.f, p_me = 0.f;
    float p_m0 = 0.f, p_m1 = 0.f, p_m2 = 0.f;

    if (rowok) {
        const float* p0 = idm + (size_t)myrow * T_STEPS * FEAT;
        ego_v = p0[0]; ego_a = p0[11]; ego_x = p0[3];
        out_disp[(size_t)myrow * (T_STEPS + 1)] = 0.0f;
        p_fv = p0[1]; p_mv = p0[2]; p_fx = p0[4]; p_mx = p0[5];
        p_fa = p0[12]; p_me = p0[13];
        const float* mp = mc + (size_t)myrow * T_STEPS * MDIM;
        p_m0 = mp[0]; p_m1 = mp[1]; p_m2 = mp[2];

        // env(t=0) packed as f16x2 pairs
        float ef_dx = p_fx - ego_x;
        float em_dx = (p_mx - ego_x) * p_me + (1.0f - p_me) * DUMMY_DX_;
        float ef_dv = ego_v - p_fv;
        float em_dv = (ego_v - p_mv) * p_me;
        float e0 = (ego_v - s->emsS[0]) * s->eisS[0];
        float e1 = (p_fv  - s->emsS[1]) * s->eisS[1];
        float e2 = (ego_a - s->emsS[2]) * s->eisS[2];
        float e3 = (p_fa  - s->emsS[3]) * s->eisS[3];
        float e4 = (ef_dv - s->emsS[4]) * s->eisS[4];
        float e5 = (ef_dx - s->emsS[5]) * s->eisS[5];
        float e6 = (em_dv - s->emsS[6]) * s->eisS[6];
        float e7 = (em_dx - s->emsS[7]) * s->eisS[7];
        uint4 pa, pb;
        pa.x = cvt2h(e1, e0); pa.y = cvt2h(e3, e2);
        pa.z = cvt2h(e5, e4); pa.w = cvt2h(e7, e6);
        pb.x = cvt2h(p_m1, p_m0); pb.y = cvt2h(0.0f, p_m2);
        pb.z = 0u; pb.w = 0u;
        *(uint4*)&s->envP[rrel][0] = pa;
        *(uint4*)&s->envP[rrel][4] = pb;

        const float* ip = idm + ((size_t)myrow * T_STEPS + 1) * FEAT;
        p_fv = ip[1]; p_mv = ip[2]; p_fx = ip[4]; p_mx = ip[5];
        p_fa = ip[12]; p_me = ip[13];
        const float* mp2 = mc + ((size_t)myrow * T_STEPS + 1) * MDIM;
        p_m0 = mp2[0]; p_m1 = mp2[1]; p_m2 = mp2[2];
    }
    const float b3v = b3[0];
    __syncthreads();

    // ================= MAIN LOOP (warp-private) =================
    for (int t = 0; t < T_STEPS; t++) {
        // ---- phase B (single-pass fp16 MMA): h1pre = base(regs) + env @ W1v ----
        float D16[16][4];
#pragma unroll
        for (int nt = 0; nt < 16; nt++) {
            float2 b01 = unpk2h(baseR01[nt]);
            float2 b23 = unpk2h(baseR23[nt]);
            D16[nt][0] = b01.x; D16[nt][1] = b01.y;
            D16[nt][2] = b23.x; D16[nt][3] = b23.y;
        }

        unsigned eh0 = s->envP[er0][ke2];
        unsigned eh1 = s->envP[er0 + 8][ke2];
        unsigned eh2 = s->envP[er0][ke2 + 4];
        unsigned eh3 = s->envP[er0 + 8][ke2 + 4];

#pragma unroll
        for (int q = 0; q < 8; q++) {
            uint4 wh = *(const uint4*)&s->w1vH[(q * 32 + lam) * 4];
            mma16816(D16[2*q][0], D16[2*q][1], D16[2*q][2], D16[2*q][3],
                     eh0, eh1, eh2, eh3, wh.x, wh.y);
            mma16816(D16[2*q+1][0], D16[2*q+1][1], D16[2*q+1][2], D16[2*q+1][3],
                     eh0, eh1, eh2, eh3, wh.z, wh.w);
        }

        // ---- leaky + single fp16 round -> phase-C A-frags ----
        unsigned ahi01[16], ahi23[16];
#pragma unroll
        for (int nt = 0; nt < 16; nt++) {
            float v0 = D16[nt][0], v1 = D16[nt][1], v2 = D16[nt][2], v3 = D16[nt][3];
            v0 = fmaxf(v0, ALPHA_ * v0);
            v1 = fmaxf(v1, ALPHA_ * v1);
            v2 = fmaxf(v2, ALPHA_ * v2);
            v3 = fmaxf(v3, ALPHA_ * v3);
            ahi01[nt] = cvt2h(v1, v0);
            ahi23[nt] = cvt2h(v3, v2);
        }

        // ---- phase C: h2 = h1 @ W2 (fp16), 4 N-sweeps, double-buffered W2 loads ----
        float pr0 = 0.0f, pr1 = 0.0f;
#pragma unroll 1
        for (int ns = 0; ns < 4; ns++) {
            float D[4][4];
#pragma unroll
            for (int nl = 0; nl < 4; nl++)
#pragma unroll
                for (int d = 0; d < 4; d++) D[nl][d] = 0.0f;

            uint4 nb0 = *(const uint4*)&s->bfragH[((2 * ns) * 32 + lam) * 4];
            uint4 nb1 = *(const uint4*)&s->bfragH[((2 * ns + 1) * 32 + lam) * 4];
#pragma unroll
            for (int kt = 0; kt < 8; kt++) {
                uint4 cb0 = nb0, cb1 = nb1;
                if (kt < 7) {
                    nb0 = *(const uint4*)&s->bfragH[(((kt + 1) * 8 + 2 * ns) * 32 + lam) * 4];
                    nb1 = *(const uint4*)&s->bfragH[(((kt + 1) * 8 + 2 * ns + 1) * 32 + lam) * 4];
                }
                unsigned a0 = ahi01[2 * kt],     a1 = ahi23[2 * kt];
                unsigned a2 = ahi01[2 * kt + 1], a3 = ahi23[2 * kt + 1];
                mma16816(D[0][0], D[0][1], D[0][2], D[0][3], a0, a1, a2, a3, cb0.x, cb0.y);
                mma16816(D[1][0], D[1][1], D[1][2], D[1][3], a0, a1, a2, a3, cb0.z, cb0.w);
                mma16816(D[2][0], D[2][1], D[2][2], D[2][3], a0, a1, a2, a3, cb1.x, cb1.y);
                mma16816(D[3][0], D[3][1], D[3][2], D[3][3], a0, a1, a2, a3, cb1.z, cb1.w);
            }
#pragma unroll
            for (int nl = 0; nl < 4; nl++) {
                int nt = 4 * ns + nl;
                float4 bw = s->b2w3F[nt * 4 + (lam & 3)];
                float v0 = D[nl][0] + bw.x;
                float v1 = D[nl][1] + bw.y;
                float v2 = D[nl][2] + bw.x;
                float v3 = D[nl][3] + bw.y;
                v0 = fmaxf(v0, ALPHA_ * v0);
                v1 = fmaxf(v1, ALPHA_ * v1);
                v2 = fmaxf(v2, ALPHA_ * v2);
                v3 = fmaxf(v3, ALPHA_ * v3);
                pr0 = fmaf(v0, bw.z, fmaf(v1, bw.w, pr0));
                pr1 = fmaf(v2, bw.z, fmaf(v3, bw.w, pr1));
            }
        }

        // ---- quad reduce over n-columns ----
        pr0 += __shfl_xor_sync(0xffffffffu, pr0, 1);
        pr0 += __shfl_xor_sync(0xffffffffu, pr0, 2);
        pr1 += __shfl_xor_sync(0xffffffffu, pr1, 1);
        pr1 += __shfl_xor_sync(0xffffffffu, pr1, 2);

        __syncwarp();   // envP reads for step t done before rewrite

        // ---- state update + outputs + env(t+1) + prefetch(t+2) ----
        if (rowok) {
            float a = ((lam & 1) ? pr1 : pr0) + b3v;
            float move = ego_v * DT_ + 0.5f * a * DT_ * DT_;
            disp  += move;
            ego_x += move;
            ego_v += a * DT_;
            ego_a  = a;
            out_act [(size_t)myrow * T_STEPS + t]           = a;
            out_disp[(size_t)myrow * (T_STEPS + 1) + t + 1] = disp;

            if (t + 1 < T_STEPS) {
                float ef_dx = p_fx - ego_x;
                float em_dx = (p_mx - ego_x) * p_me + (1.0f - p_me) * DUMMY_DX_;
                float ef_dv = ego_v - p_fv;
                float em_dv = (ego_v - p_mv) * p_me;
                float e0 = (ego_v - s->emsS[0]) * s->eisS[0];
                float e1 = (p_fv  - s->emsS[1]) * s->eisS[1];
                float e2 = (ego_a - s->emsS[2]) * s->eisS[2];
                float e3 = (p_fa  - s->emsS[3]) * s->eisS[3];
                float e4 = (ef_dv - s->emsS[4]) * s->eisS[4];
                float e5 = (ef_dx - s->emsS[5]) * s->eisS[5];
                float e6 = (em_dv - s->emsS[6]) * s->eisS[6];
                float e7 = (em_dx - s->emsS[7]) * s->eisS[7];
                uint4 pa, pb;
                pa.x = cvt2h(e1, e0); pa.y = cvt2h(e3, e2);
                pa.z = cvt2h(e5, e4); pa.w = cvt2h(e7, e6);
                pb.x = cvt2h(p_m1, p_m0); pb.y = cvt2h(0.0f, p_m2);
                pb.z = 0u; pb.w = 0u;
                *(uint4*)&s->envP[rrel][0] = pa;
                *(uint4*)&s->envP[rrel][4] = pb;

                int tn = (t + 2 < T_STEPS) ? t + 2 : T_STEPS - 1;
                const float* ip = idm + ((size_t)myrow * T_STEPS + tn) * FEAT;
                p_fv = ip[1]; p_mv = ip[2]; p_fx = ip[4]; p_mx = ip[5];
                p_fa = ip[12]; p_me = ip[13];
                const float* mp = mc + ((size_t)myrow * T_STEPS + tn) * MDIM;
                p_m0 = mp[0]; p_m1 = mp[1]; p_m2 = mp[2];
            }
        }
        __syncwarp();   // env writes visible before next iteration's reads
    }
}

extern "C" void kernel_launch(void* const* d_in, const int* in_sizes, int n_in,
                              void* d_out, int out_size) {
    const float* proj     = (const float*)d_in[0];
    const float* enc      = (const float*)d_in[1];
    const float* idm      = (const float*)d_in[2];
    const float* mc       = (const float*)d_in[3];
    const float* env_mean = (const float*)d_in[4];
    const float* env_var  = (const float*)d_in[5];
    const float* W1       = (const float*)d_in[6];
    const float* b1       = (const float*)d_in[7];
    const float* W2       = (const float*)d_in[8];
    const float* b2       = (const float*)d_in[9];
    const float* W3       = (const float*)d_in[10];
    const float* b3       = (const float*)d_in[11];
    float* out = (float*)d_out;

    int B = in_sizes[0] / 128;

    int smem = (int)sizeof(Smem);
    cudaFuncSetAttribute(forward_sim_kernel,
                         cudaFuncAttributeMaxDynamicSharedMemorySize, smem);

    dim3 grid((B + ROWS - 1) / ROWS);
    forward_sim_kernel<<<grid, THREADS, smem>>>(
        proj, enc, idm, mc, env_mean, env_var,
        W1, b1, W2, b2, W3, b3, out, B);
}